// round 14
// baseline (speedup 1.0000x reference)
#include <cuda_runtime.h>
#include <cuda_fp16.h>
#include <cstdint>
#include <cstddef>

// ---------------- problem constants ----------------
#define E_EXP 8
#define TOPK  2
#define DM    1024
#define HD    4096
#define NTOK  4096           // B*T = 2*2048
#define LN_EPS 1e-5f
#define INV_TEMP (1.0f/1.5f)

// ---------------- GEMM tile config ----------------
#define BM 128
#define BN 128
#define BK 32                // halves per K step
#define NSTG 3
#define ASTRH 40             // A smem row stride in halves (80B, conflict-free ldmatrix)
#define BSTRH 136            // B smem row stride in halves (272B)
#define A_STG_H (BM * ASTRH)             // 5120 halves = 10240 B
#define B_STG_H (BK * BSTRH)             // 4352 halves = 8704 B
#define SLOT_BH (A_STG_H * 2)            // fp16 B offset within slot
#define SLOT_BF (A_STG_H * 2 + B_STG_H * 2)  // fp32 B staging offset (18944)
#define BF32_STG (BK * 512)              // 32 rows x 128 floats = 16384 B
#define SLOT_BYTES (SLOT_BF + BF32_STG)  // 35328 B (16B aligned)
#define DYN_BYTES (NSTG * SLOT_BYTES)    // 105984 B (x2 CTAs = 211968 <= 228KB)

#define ROWPAD 512
#define HROWS  (NTOK * TOPK + ROWPAD)

// ---------------- device scratch (static; no allocations) ----------------
__device__ __half g_xn[(size_t)NTOK * DM];
__device__ int    g_cnt[E_EXP];
__device__ int    g_off[E_EXP];
__device__ int    g_tok[E_EXP * NTOK];
__device__ int    g_tslot[NTOK * TOPK];
__device__ float  g_twt[NTOK * TOPK];
__device__ __half g_h[(size_t)HROWS * HD];            // 68 MB
__device__ float  g_y[(size_t)HROWS * DM];            // 34 MB

// ---------------- PTX helpers ----------------
__device__ __forceinline__ uint32_t smem_u32(const void* p) {
    return (uint32_t)__cvta_generic_to_shared(p);
}
__device__ __forceinline__ void cp16(uint32_t dst, const void* src, int src_bytes) {
    asm volatile("cp.async.cg.shared.global [%0], [%1], 16, %2;\n"
                 :: "r"(dst), "l"(src), "r"(src_bytes) : "memory");
}
__device__ __forceinline__ void cp_commit() {
    asm volatile("cp.async.commit_group;\n" ::: "memory");
}
__device__ __forceinline__ void sts64(uint32_t dst, uint32_t v0, uint32_t v1) {
    asm volatile("st.shared.v2.b32 [%0], {%1,%2};\n" :: "r"(dst), "r"(v0), "r"(v1) : "memory");
}
__device__ __forceinline__ void lds128f(float4& v, uint32_t addr) {
    asm volatile("ld.shared.v4.f32 {%0,%1,%2,%3}, [%4];"
                 : "=f"(v.x), "=f"(v.y), "=f"(v.z), "=f"(v.w) : "r"(addr));
}
__device__ __forceinline__ void ldsm4(uint32_t* r, uint32_t addr) {
    asm volatile("ldmatrix.sync.aligned.m8n8.x4.shared.b16 {%0,%1,%2,%3}, [%4];"
                 : "=r"(r[0]), "=r"(r[1]), "=r"(r[2]), "=r"(r[3]) : "r"(addr));
}
__device__ __forceinline__ void ldsm4t(uint32_t* r, uint32_t addr) {
    asm volatile("ldmatrix.sync.aligned.m8n8.x4.trans.shared.b16 {%0,%1,%2,%3}, [%4];"
                 : "=r"(r[0]), "=r"(r[1]), "=r"(r[2]), "=r"(r[3]) : "r"(addr));
}
__device__ __forceinline__ void mma_f16(float* c, const uint32_t* a, const uint32_t* b) {
    asm volatile(
        "mma.sync.aligned.m16n8k16.row.col.f32.f16.f16.f32 "
        "{%0,%1,%2,%3}, {%4,%5,%6,%7}, {%8,%9}, {%0,%1,%2,%3};\n"
        : "+f"(c[0]), "+f"(c[1]), "+f"(c[2]), "+f"(c[3])
        : "r"(a[0]), "r"(a[1]), "r"(a[2]), "r"(a[3]), "r"(b[0]), "r"(b[1]));
}
__device__ __forceinline__ float silu(float v) { return v / (1.0f + expf(-v)); }

// ---------------- kernel 0: zero counters ----------------
__global__ void k_init() {
    if (threadIdx.x < E_EXP) g_cnt[threadIdx.x] = 0;
}

// ---------------- kernel 1: layernorm + router + top2 ----------------
__global__ void k_ln_router(const float* __restrict__ x,
                            const float* __restrict__ gamma,
                            const float* __restrict__ beta,
                            const float* __restrict__ rw) {
    int t = blockIdx.x;
    int tid = threadIdx.x;
    int warp = tid >> 5, lane = tid & 31;

    const float4 v = reinterpret_cast<const float4*>(x + (size_t)t * DM)[tid];
    float s  = v.x + v.y + v.z + v.w;
    float ss = v.x * v.x + v.y * v.y + v.z * v.z + v.w * v.w;
    #pragma unroll
    for (int o = 16; o; o >>= 1) {
        s  += __shfl_xor_sync(0xFFFFFFFFu, s,  o);
        ss += __shfl_xor_sync(0xFFFFFFFFu, ss, o);
    }
    __shared__ float sh_s[8], sh_ss[8];
    if (lane == 0) { sh_s[warp] = s; sh_ss[warp] = ss; }
    __syncthreads();
    float st = 0.f, sst = 0.f;
    #pragma unroll
    for (int i = 0; i < 8; i++) { st += sh_s[i]; sst += sh_ss[i]; }
    float mu   = st * (1.0f / DM);
    float var  = sst * (1.0f / DM) - mu * mu;
    float rstd = rsqrtf(var + LN_EPS);

    const float4 g = reinterpret_cast<const float4*>(gamma)[tid];
    const float4 b = reinterpret_cast<const float4*>(beta)[tid];
    float4 xn;
    xn.x = (v.x - mu) * rstd * g.x + b.x;
    xn.y = (v.y - mu) * rstd * g.y + b.y;
    xn.z = (v.z - mu) * rstd * g.z + b.z;
    xn.w = (v.w - mu) * rstd * g.w + b.w;
    {
        __half2 h0 = __floats2half2_rn(xn.x, xn.y);
        __half2 h1 = __floats2half2_rn(xn.z, xn.w);
        uint2 u;
        u.x = *reinterpret_cast<uint32_t*>(&h0);
        u.y = *reinterpret_cast<uint32_t*>(&h1);
        reinterpret_cast<uint2*>(g_xn + (size_t)t * DM)[tid] = u;
    }

    float acc[E_EXP];
    #pragma unroll
    for (int e = 0; e < E_EXP; e++) {
        const float4 w = reinterpret_cast<const float4*>(rw + (size_t)e * DM)[tid];
        acc[e] = xn.x * w.x + xn.y * w.y + xn.z * w.z + xn.w * w.w;
    }
    #pragma unroll
    for (int o = 16; o; o >>= 1) {
        #pragma unroll
        for (int e = 0; e < E_EXP; e++)
            acc[e] += __shfl_xor_sync(0xFFFFFFFFu, acc[e], o);
    }
    __shared__ float sh_l[8][E_EXP];
    if (lane == 0) {
        #pragma unroll
        for (int e = 0; e < E_EXP; e++) sh_l[warp][e] = acc[e];
    }
    __syncthreads();

    if (tid == 0) {
        float lg[E_EXP];
        #pragma unroll
        for (int e = 0; e < E_EXP; e++) {
            float a = 0.f;
            #pragma unroll
            for (int w = 0; w < 8; w++) a += sh_l[w][e];
            lg[e] = a * INV_TEMP;
        }
        float mx = lg[0];
        #pragma unroll
        for (int e = 1; e < E_EXP; e++) mx = fmaxf(mx, lg[e]);
        float p[E_EXP], sum = 0.f;
        #pragma unroll
        for (int e = 0; e < E_EXP; e++) { p[e] = expf(lg[e] - mx); sum += p[e]; }
        float inv = 1.0f / sum;
        int i1 = 0;
        #pragma unroll
        for (int e = 1; e < E_EXP; e++) if (p[e] > p[i1]) i1 = e;
        int i2 = (i1 == 0) ? 1 : 0;
        #pragma unroll
        for (int e = 0; e < E_EXP; e++) if (e != i1 && p[e] > p[i2]) i2 = e;

        int pos1 = atomicAdd(&g_cnt[i1], 1);
        int pos2 = atomicAdd(&g_cnt[i2], 1);
        g_tok[i1 * NTOK + pos1] = t;
        g_tok[i2 * NTOK + pos2] = t;
        g_tslot[2 * t + 0] = (i1 << 24) | pos1;
        g_tslot[2 * t + 1] = (i2 << 24) | pos2;
        g_twt[2 * t + 0] = p[i1] * inv;
        g_twt[2 * t + 1] = p[i2] * inv;
    }
}

// ---------------- kernel 2: prefix offsets ----------------
__global__ void k_off() {
    if (threadIdx.x == 0) {
        int o = 0;
        #pragma unroll
        for (int e = 0; e < E_EXP; e++) { g_off[e] = o; o += g_cnt[e]; }
    }
}

// ---------------- grouped GEMM: all global traffic on cp.async; B cvt SMEM->SMEM ----------------
// MODE 0: g_h[off+m, :] = half( silu(xn[tok] @ W1[e]) )   (K=DM, N=HD)
// MODE 1: g_y[off+m, :] = float( g_h[off+m, :] @ W2[e] )  (K=HD, N=DM)
template <int MODE>
__global__ __launch_bounds__(256, 2)
void k_gemm(const float* __restrict__ Bw) {
    constexpr int KDIM = (MODE == 0) ? DM : HD;
    constexpr int BLD  = (MODE == 0) ? HD : DM;    // weight row stride (= N extent)
    constexpr int NKB  = KDIM / BK;

    const int e   = blockIdx.z;
    const int m0  = blockIdx.y * BM;
    const int n0  = blockIdx.x * BN;
    const int cnt = g_cnt[e];
    if (m0 >= cnt) return;
    const int off = g_off[e];
    const int tid = threadIdx.x;

    extern __shared__ __half smh[];
    const uint32_t dyn_s = smem_u32(smh);

    __shared__ int tok_s[BM];
    if (MODE == 0) {
        if (tid < BM) {
            int m = m0 + tid;
            tok_s[tid] = (m < cnt) ? g_tok[e * NTOK + m] : -1;
        }
        __syncthreads();
    }

    const float* Bbase = Bw + (size_t)e * KDIM * BLD + n0;
    const int b_row0 = tid >> 5;          // 0..7; thread's fp32-B rows: b_row0 + 8i
    const int b_col4 = tid & 31;          // 16B column chunk

    // ---- stage loader: A fp16 (2 cp16) + B fp32 staging (4 cp16), ONE commit group ----
    auto load_stage = [&](int kb, uint32_t slot_byte) {
        const uint32_t s0 = dyn_s + slot_byte;
        #pragma unroll
        for (int i = 0; i < 2; i++) {
            int seg = tid + i * 256;
            int row = seg >> 2;
            int j   = seg & 3;            // 16B chunk = 8 halves
            uint32_t dst = s0 + (row * ASTRH + j * 8) * 2;
            const __half* src;
            int sz = 16;
            if (MODE == 0) {
                int token = tok_s[row];
                if (token < 0) { src = g_xn; sz = 0; }
                else            src = g_xn + (size_t)token * DM + kb * BK + j * 8;
            } else {
                src = g_h + (size_t)(off + m0 + row) * HD + kb * BK + j * 8;
            }
            cp16(dst, src, sz);
        }
        const float* bp = Bbase + (size_t)(kb * BK + b_row0) * BLD + b_col4 * 4;
        const uint32_t bf = s0 + SLOT_BF + b_row0 * 512 + b_col4 * 16;
        #pragma unroll
        for (int i = 0; i < 4; i++)
            cp16(bf + i * (8 * 512), bp + (size_t)(i * 8) * BLD, 16);
        cp_commit();
    };

    // ---- convert: thread reads ITS OWN staged fp32 chunks, writes fp16 B tile ----
    const uint32_t cvt_src_off = SLOT_BF + b_row0 * 512 + b_col4 * 16;
    const uint32_t cvt_dst_off = SLOT_BH + (b_row0 * BSTRH + b_col4 * 4) * 2;
    auto convert_B = [&](uint32_t slot_byte) {
        const uint32_t sf = dyn_s + slot_byte + cvt_src_off;
        const uint32_t sh = dyn_s + slot_byte + cvt_dst_off;
        float4 v[4];
        #pragma unroll
        for (int i = 0; i < 4; i++) lds128f(v[i], sf + i * (8 * 512));
        #pragma unroll
        for (int i = 0; i < 4; i++) {
            __half2 h0 = __floats2half2_rn(v[i].x, v[i].y);
            __half2 h1 = __floats2half2_rn(v[i].z, v[i].w);
            sts64(sh + i * (8 * BSTRH * 2),
                  *reinterpret_cast<uint32_t*>(&h0), *reinterpret_cast<uint32_t*>(&h1));
        }
    };

    const int warp = tid >> 5, lane = tid & 31;
    const int wr = warp & 3, wc = warp >> 2;     // 4x2 warp grid
    const int wm = wr * 32, wn = wc * 64;        // warp tile 32x64
    const int lr = lane >> 2, lc = lane & 3;

    const uint32_t a_off0 = ((wm + (lane & 15)) * ASTRH + ((lane >> 4) * 8)) * 2;
    const uint32_t b_off0 = SLOT_BH + ((lane & 15) * BSTRH + wn + ((lane >> 4) * 8)) * 2;

    float acc[2][8][4];
    #pragma unroll
    for (int mt = 0; mt < 2; mt++)
        #pragma unroll
        for (int nt = 0; nt < 8; nt++)
            #pragma unroll
            for (int i = 0; i < 4; i++) acc[mt][nt][i] = 0.f;

    // prologue: stages 0,1 in flight; convert stage 0 (own data, wait_group only)
    load_stage(0, 0);
    load_stage(1, SLOT_BYTES);
    asm volatile("cp.async.wait_group 1;\n" ::: "memory");
    convert_B(0);

    uint32_t st_cur = 0;
    uint32_t st_n1  = SLOT_BYTES;
    uint32_t st_n2  = 2 * SLOT_BYTES;

    for (int kb = 0; kb < NKB; kb++) {
        // leading wait: stage kb's group complete (per-thread), then barrier for
        // cross-thread visibility + slot-drain; only THEN recycle slot kb+2.
        if (kb + 1 < NKB) {
            asm volatile("cp.async.wait_group 1;\n" ::: "memory");
        } else {
            asm volatile("cp.async.wait_group 0;\n" ::: "memory");
        }
        __syncthreads();
        if (kb + 2 < NKB) load_stage(kb + 2, st_n2);

        const uint32_t a_base = dyn_s + st_cur + a_off0;
        const uint32_t b_base = dyn_s + st_cur + b_off0;

        #pragma unroll
        for (int ks = 0; ks < 2; ks++) {
            const uint32_t kbyte = ks * 32;
            uint32_t af[2][4];
            #pragma unroll
            for (int mt = 0; mt < 2; mt++)
                ldsm4(af[mt], a_base + mt * (16 * ASTRH * 2) + kbyte);
            uint32_t bf[4][4];
            #pragma unroll
            for (int np = 0; np < 4; np++)
                ldsm4t(bf[np], b_base + ks * (16 * BSTRH * 2) + np * 32);
            #pragma unroll
            for (int mt = 0; mt < 2; mt++)
                #pragma unroll
                for (int nt = 0; nt < 8; nt++)
                    mma_f16(acc[mt][nt], af[mt], &bf[nt >> 1][(nt & 1) * 2]);
        }

        // convert stage kb+1 (reads own staged fp32 -> needs only own wait_group;
        // its fp16 output is read by others only after next iteration's barrier)
        if (kb + 1 < NKB) {
            if (kb + 2 < NKB) {
                asm volatile("cp.async.wait_group 1;\n" ::: "memory");
            } else {
                asm volatile("cp.async.wait_group 0;\n" ::: "memory");
            }
            convert_B(st_n1);
        }

        uint32_t t = st_cur; st_cur = st_n1; st_n1 = st_n2; st_n2 = t;
    }

    // ---- epilogue ----
    #pragma unroll
    for (int mt = 0; mt < 2; mt++) {
        #pragma unroll
        for (int nt = 0; nt < 8; nt++) {
            int gm0 = m0 + wm + mt * 16 + lr;
            int gn  = n0 + wn + nt * 8 + lc * 2;
            float* c = acc[mt][nt];
            if (MODE == 0) {
                if (gm0 < cnt) {
                    __half2 h = __floats2half2_rn(silu(c[0]), silu(c[1]));
                    *reinterpret_cast<__half2*>(&g_h[(size_t)(off + gm0) * HD + gn]) = h;
                }
                if (gm0 + 8 < cnt) {
                    __half2 h = __floats2half2_rn(silu(c[2]), silu(c[3]));
                    *reinterpret_cast<__half2*>(&g_h[(size_t)(off + gm0 + 8) * HD + gn]) = h;
                }
            } else {
                if (gm0 < cnt) {
                    float2 r0 = make_float2(c[0], c[1]);
                    *reinterpret_cast<float2*>(&g_y[(size_t)(off + gm0) * DM + gn]) = r0;
                }
                if (gm0 + 8 < cnt) {
                    float2 r1 = make_float2(c[2], c[3]);
                    *reinterpret_cast<float2*>(&g_y[(size_t)(off + gm0 + 8) * DM + gn]) = r1;
                }
            }
        }
    }
}

// ---------------- kernel 5: deterministic combine ----------------
__global__ void k_combine(const float* __restrict__ x, float* __restrict__ out) {
    int t = blockIdx.x;
    int tid = threadIdx.x;
    int s0 = g_tslot[2 * t + 0];
    int s1 = g_tslot[2 * t + 1];
    float w0 = g_twt[2 * t + 0];
    float w1 = g_twt[2 * t + 1];
    int r0 = g_off[s0 >> 24] + (s0 & 0xFFFFFF);
    int r1 = g_off[s1 >> 24] + (s1 & 0xFFFFFF);

    float4 xv = reinterpret_cast<const float4*>(x + (size_t)t * DM)[tid];
    float4 y0 = reinterpret_cast<const float4*>(g_y + (size_t)r0 * DM)[tid];
    float4 y1 = reinterpret_cast<const float4*>(g_y + (size_t)r1 * DM)[tid];
    float4 o;
    o.x = xv.x + w0 * y0.x + w1 * y1.x;
    o.y = xv.y + w0 * y0.y + w1 * y1.y;
    o.z = xv.z + w0 * y0.z + w1 * y1.z;
    o.w = xv.w + w0 * y0.w + w1 * y1.w;
    reinterpret_cast<float4*>(out + (size_t)t * DM)[tid] = o;
}

// ---------------- launcher (serial; streams proven non-overlapping here) ----------------
extern "C" void kernel_launch(void* const* d_in, const int* in_sizes, int n_in,
                              void* d_out, int out_size) {
    const float* x     = (const float*)d_in[0];
    const float* gamma = (const float*)d_in[1];
    const float* beta  = (const float*)d_in[2];
    const float* rw    = (const float*)d_in[3];
    const float* W1    = (const float*)d_in[4];
    const float* W2    = (const float*)d_in[5];
    float* out = (float*)d_out;

    cudaFuncSetAttribute(k_gemm<0>, cudaFuncAttributeMaxDynamicSharedMemorySize, DYN_BYTES);
    cudaFuncSetAttribute(k_gemm<1>, cudaFuncAttributeMaxDynamicSharedMemorySize, DYN_BYTES);

    k_init<<<1, 32>>>();
    k_ln_router<<<NTOK, 256>>>(x, gamma, beta, rw);
    k_off<<<1, 1>>>();
    // GEMM1: N=HD -> 32 n-tiles; M tiles of 128; 8 experts
    k_gemm<0><<<dim3(HD / BN, NTOK / BM, E_EXP), 256, DYN_BYTES>>>(W1);
    // GEMM2: N=DM -> 8 n-tiles
    k_gemm<1><<<dim3(DM / BN, NTOK / BM, E_EXP), 256, DYN_BYTES>>>(W2);
    k_combine<<<NTOK, 256>>>(x, out);
}

// round 15
// speedup vs baseline: 1.0836x; 1.0836x over previous
#include <cuda_runtime.h>
#include <cuda_fp16.h>
#include <cstdint>
#include <cstddef>

// ---------------- problem constants ----------------
#define E_EXP 8
#define TOPK  2
#define DM    1024
#define HD    4096
#define NTOK  4096           // B*T = 2*2048
#define LN_EPS 1e-5f
#define INV_TEMP (1.0f/1.5f)

// ---------------- GEMM tile config (R9-proven: fp16 mma.sync + ldmatrix, fused fp32 B cvt) ----
#define BM 128
#define BN 128
#define BK 32                // halves per K step
#define NSTG 4
#define ASTRH 40             // A smem row stride in halves (80B, conflict-free ldmatrix)
#define BSTRH 136            // B smem row stride in halves (272B)
#define A_STG_H (BM * ASTRH)             // 5120 halves
#define B_STG_H (BK * BSTRH)             // 4352 halves
#define STG_H   (A_STG_H + B_STG_H)      // 9472 halves = 18944 B
#define STG_B   (STG_H * 2)
#define DYN_BYTES (NSTG * STG_B)         // 75776 B (x2 CTAs/SM)

#define ROWPAD 512
#define HROWS  (NTOK * TOPK + ROWPAD)

// ---------------- device scratch (static; no allocations) ----------------
__device__ __half g_xn[(size_t)NTOK * DM];
__device__ int    g_cnt[E_EXP];
__device__ int    g_tok[E_EXP * NTOK];
__device__ int    g_tslot[NTOK * TOPK];
__device__ float  g_twt[NTOK * TOPK];
__device__ __half g_h[(size_t)HROWS * HD];            // 68 MB
__device__ float  g_y[(size_t)HROWS * DM];            // 34 MB

// ---------------- PTX helpers ----------------
__device__ __forceinline__ uint32_t smem_u32(const void* p) {
    return (uint32_t)__cvta_generic_to_shared(p);
}
__device__ __forceinline__ void cp16(uint32_t dst, const void* src, int src_bytes) {
    asm volatile("cp.async.cg.shared.global [%0], [%1], 16, %2;\n"
                 :: "r"(dst), "l"(src), "r"(src_bytes) : "memory");
}
__device__ __forceinline__ void cp_commit() {
    asm volatile("cp.async.commit_group;\n" ::: "memory");
}
__device__ __forceinline__ void sts64(uint32_t dst, uint32_t v0, uint32_t v1) {
    asm volatile("st.shared.v2.b32 [%0], {%1,%2};\n" :: "r"(dst), "r"(v0), "r"(v1) : "memory");
}
__device__ __forceinline__ void ldsm4(uint32_t* r, uint32_t addr) {
    asm volatile("ldmatrix.sync.aligned.m8n8.x4.shared.b16 {%0,%1,%2,%3}, [%4];"
                 : "=r"(r[0]), "=r"(r[1]), "=r"(r[2]), "=r"(r[3]) : "r"(addr));
}
__device__ __forceinline__ void ldsm4t(uint32_t* r, uint32_t addr) {
    asm volatile("ldmatrix.sync.aligned.m8n8.x4.trans.shared.b16 {%0,%1,%2,%3}, [%4];"
                 : "=r"(r[0]), "=r"(r[1]), "=r"(r[2]), "=r"(r[3]) : "r"(addr));
}
__device__ __forceinline__ void mma_f16(float* c, const uint32_t* a, const uint32_t* b) {
    asm volatile(
        "mma.sync.aligned.m16n8k16.row.col.f32.f16.f16.f32 "
        "{%0,%1,%2,%3}, {%4,%5,%6,%7}, {%8,%9}, {%0,%1,%2,%3};\n"
        : "+f"(c[0]), "+f"(c[1]), "+f"(c[2]), "+f"(c[3])
        : "r"(a[0]), "r"(a[1]), "r"(a[2]), "r"(a[3]), "r"(b[0]), "r"(b[1]));
}
__device__ __forceinline__ float silu(float v) { return v / (1.0f + expf(-v)); }

// inline prefix-sum of g_cnt[0..e-1] (replaces the k_off kernel)
__device__ __forceinline__ int expert_off(int e) {
    int o = 0;
    #pragma unroll
    for (int i = 0; i < E_EXP; i++) if (i < e) o += g_cnt[i];
    return o;
}

// ---------------- kernel 0: zero counters ----------------
__global__ void k_init() {
    if (threadIdx.x < E_EXP) g_cnt[threadIdx.x] = 0;
}

// ---------------- kernel 1: layernorm + router + top2 ----------------
__global__ void k_ln_router(const float* __restrict__ x,
                            const float* __restrict__ gamma,
                            const float* __restrict__ beta,
                            const float* __restrict__ rw) {
    int t = blockIdx.x;
    int tid = threadIdx.x;
    int warp = tid >> 5, lane = tid & 31;

    const float4 v = reinterpret_cast<const float4*>(x + (size_t)t * DM)[tid];
    float s  = v.x + v.y + v.z + v.w;
    float ss = v.x * v.x + v.y * v.y + v.z * v.z + v.w * v.w;
    #pragma unroll
    for (int o = 16; o; o >>= 1) {
        s  += __shfl_xor_sync(0xFFFFFFFFu, s,  o);
        ss += __shfl_xor_sync(0xFFFFFFFFu, ss, o);
    }
    __shared__ float sh_s[8], sh_ss[8];
    if (lane == 0) { sh_s[warp] = s; sh_ss[warp] = ss; }
    __syncthreads();
    float st = 0.f, sst = 0.f;
    #pragma unroll
    for (int i = 0; i < 8; i++) { st += sh_s[i]; sst += sh_ss[i]; }
    float mu   = st * (1.0f / DM);
    float var  = sst * (1.0f / DM) - mu * mu;
    float rstd = rsqrtf(var + LN_EPS);

    const float4 g = reinterpret_cast<const float4*>(gamma)[tid];
    const float4 b = reinterpret_cast<const float4*>(beta)[tid];
    float4 xn;
    xn.x = (v.x - mu) * rstd * g.x + b.x;
    xn.y = (v.y - mu) * rstd * g.y + b.y;
    xn.z = (v.z - mu) * rstd * g.z + b.z;
    xn.w = (v.w - mu) * rstd * g.w + b.w;
    {
        __half2 h0 = __floats2half2_rn(xn.x, xn.y);
        __half2 h1 = __floats2half2_rn(xn.z, xn.w);
        uint2 u;
        u.x = *reinterpret_cast<uint32_t*>(&h0);
        u.y = *reinterpret_cast<uint32_t*>(&h1);
        reinterpret_cast<uint2*>(g_xn + (size_t)t * DM)[tid] = u;
    }

    float acc[E_EXP];
    #pragma unroll
    for (int e = 0; e < E_EXP; e++) {
        const float4 w = reinterpret_cast<const float4*>(rw + (size_t)e * DM)[tid];
        acc[e] = xn.x * w.x + xn.y * w.y + xn.z * w.z + xn.w * w.w;
    }
    #pragma unroll
    for (int o = 16; o; o >>= 1) {
        #pragma unroll
        for (int e = 0; e < E_EXP; e++)
            acc[e] += __shfl_xor_sync(0xFFFFFFFFu, acc[e], o);
    }
    __shared__ float sh_l[8][E_EXP];
    if (lane == 0) {
        #pragma unroll
        for (int e = 0; e < E_EXP; e++) sh_l[warp][e] = acc[e];
    }
    __syncthreads();

    if (tid == 0) {
        float lg[E_EXP];
        #pragma unroll
        for (int e = 0; e < E_EXP; e++) {
            float a = 0.f;
            #pragma unroll
            for (int w = 0; w < 8; w++) a += sh_l[w][e];
            lg[e] = a * INV_TEMP;
        }
        float mx = lg[0];
        #pragma unroll
        for (int e = 1; e < E_EXP; e++) mx = fmaxf(mx, lg[e]);
        float p[E_EXP], sum = 0.f;
        #pragma unroll
        for (int e = 0; e < E_EXP; e++) { p[e] = expf(lg[e] - mx); sum += p[e]; }
        float inv = 1.0f / sum;
        int i1 = 0;
        #pragma unroll
        for (int e = 1; e < E_EXP; e++) if (p[e] > p[i1]) i1 = e;
        int i2 = (i1 == 0) ? 1 : 0;
        #pragma unroll
        for (int e = 0; e < E_EXP; e++) if (e != i1 && p[e] > p[i2]) i2 = e;

        int pos1 = atomicAdd(&g_cnt[i1], 1);
        int pos2 = atomicAdd(&g_cnt[i2], 1);
        g_tok[i1 * NTOK + pos1] = t;
        g_tok[i2 * NTOK + pos2] = t;
        g_tslot[2 * t + 0] = (i1 << 24) | pos1;
        g_tslot[2 * t + 1] = (i2 << 24) | pos2;
        g_twt[2 * t + 0] = p[i1] * inv;
        g_twt[2 * t + 1] = p[i2] * inv;
    }
}

// ---------------- grouped GEMM (R9-proven; fp16 mma.sync; B converted fp32->fp16 in-flight) ----
// MODE 0: g_h[off+m, :] = half( silu(xn[tok] @ W1[e]) )   (K=DM, N=HD)
// MODE 1: g_y[off+m, :] = float( g_h[off+m, :] @ W2[e] )  (K=HD, N=DM)
template <int MODE>
__global__ __launch_bounds__(256, 2)
void k_gemm(const float* __restrict__ Bw) {
    constexpr int KDIM = (MODE == 0) ? DM : HD;
    constexpr int BLD  = (MODE == 0) ? HD : DM;    // weight row stride (= N extent)
    constexpr int NKB  = KDIM / BK;

    const int e   = blockIdx.z;
    const int m0  = blockIdx.y * BM;
    const int n0  = blockIdx.x * BN;
    const int cnt = g_cnt[e];
    if (m0 >= cnt) return;
    const int off = expert_off(e);
    const int tid = threadIdx.x;

    extern __shared__ __half smh[];
    const uint32_t dyn_s = smem_u32(smh);

    __shared__ int tok_s[BM];
    if (MODE == 0) {
        if (tid < BM) {
            int m = m0 + tid;
            tok_s[tid] = (m < cnt) ? g_tok[e * NTOK + m] : -1;
        }
        __syncthreads();
    }

    // ---- A stage loader: cp.async fp16 ----
    auto load_A = [&](int kb, int s) {
        const uint32_t a_s = dyn_s + (uint32_t)s * STG_B;
        #pragma unroll
        for (int i = 0; i < 2; i++) {
            int seg = tid + i * 256;
            int row = seg >> 2;
            int j   = seg & 3;            // 16B chunk = 8 halves
            uint32_t dst = a_s + (row * ASTRH + j * 8) * 2;
            const __half* src;
            int sz = 16;
            if (MODE == 0) {
                int token = tok_s[row];
                if (token < 0) { src = g_xn; sz = 0; }
                else            src = g_xn + (size_t)token * DM + kb * BK + j * 8;
            } else {
                src = g_h + (size_t)(off + m0 + row) * HD + kb * BK + j * 8;
            }
            cp16(dst, src, sz);
        }
        cp_commit();
    };

    // ---- B: fp32 LDG into registers, cvt+STS fp16 (pipelined around MMA) ----
    const float* Bbase = Bw + (size_t)e * KDIM * BLD + n0;
    const int b_row0 = tid >> 5;          // rows b_row0, +8, +16, +24
    const int b_col4 = tid & 31;

    float4 breg[4];
    auto ldg_B = [&](int kb) {
        const float* bp = Bbase + (size_t)(kb * BK + b_row0) * BLD + b_col4 * 4;
        #pragma unroll
        for (int i = 0; i < 4; i++)
            breg[i] = *reinterpret_cast<const float4*>(bp + (size_t)(i * 8) * BLD);
    };
    const uint32_t b_sts_off = A_STG_H * 2 + (b_row0 * BSTRH + b_col4 * 4) * 2;
    auto sts_B = [&](uint32_t stage_byte) {
        const uint32_t b_s = dyn_s + stage_byte + b_sts_off;
        #pragma unroll
        for (int i = 0; i < 4; i++) {
            __half2 h0 = __floats2half2_rn(breg[i].x, breg[i].y);
            __half2 h1 = __floats2half2_rn(breg[i].z, breg[i].w);
            sts64(b_s + (i * 8 * BSTRH) * 2,
                  *reinterpret_cast<uint32_t*>(&h0), *reinterpret_cast<uint32_t*>(&h1));
        }
    };

    const int warp = tid >> 5, lane = tid & 31;
    const int wr = warp & 3, wc = warp >> 2;     // 4x2 warp grid
    const int wm = wr * 32, wn = wc * 64;        // warp tile 32x64
    const int lr = lane >> 2, lc = lane & 3;

    const uint32_t a_off0 = ((wm + (lane & 15)) * ASTRH + ((lane >> 4) * 8)) * 2;
    const uint32_t b_off0 = A_STG_H * 2 + ((lane & 15) * BSTRH + wn + ((lane >> 4) * 8)) * 2;

    float acc[2][8][4];
    #pragma unroll
    for (int mt = 0; mt < 2; mt++)
        #pragma unroll
        for (int nt = 0; nt < 8; nt++)
            #pragma unroll
            for (int i = 0; i < 4; i++) acc[mt][nt][i] = 0.f;

    // prologue
    load_A(0, 0);
    load_A(1, 1);
    load_A(2, 2);
    ldg_B(0);
    sts_B(0);
    ldg_B(1);

    uint32_t st_off = 0;
    uint32_t st_nxt = STG_B;

    for (int kb = 0; kb < NKB; kb++) {
        if (kb + 3 < NKB) {
            load_A(kb + 3, (kb + 3) & 3);
            asm volatile("cp.async.wait_group 3;\n" ::: "memory");
        } else if (kb + 2 < NKB) {
            asm volatile("cp.async.wait_group 2;\n" ::: "memory");
        } else if (kb + 1 < NKB) {
            asm volatile("cp.async.wait_group 1;\n" ::: "memory");
        } else {
            asm volatile("cp.async.wait_group 0;\n" ::: "memory");
        }
        __syncthreads();

        const uint32_t a_base = dyn_s + st_off + a_off0;
        const uint32_t b_base = dyn_s + st_off + b_off0;

        #pragma unroll
        for (int ks = 0; ks < 2; ks++) {
            const uint32_t kbyte = ks * 32;
            uint32_t af[2][4];
            #pragma unroll
            for (int mt = 0; mt < 2; mt++)
                ldsm4(af[mt], a_base + mt * (16 * ASTRH * 2) + kbyte);
            uint32_t bf[4][4];
            #pragma unroll
            for (int np = 0; np < 4; np++)
                ldsm4t(bf[np], b_base + ks * (16 * BSTRH * 2) + np * 32);
            #pragma unroll
            for (int mt = 0; mt < 2; mt++)
                #pragma unroll
                for (int nt = 0; nt < 8; nt++)
                    mma_f16(acc[mt][nt], af[mt], &bf[nt >> 1][(nt & 1) * 2]);
        }

        // B pipeline after the MMA block. ldg_B for kb+2 issues BEFORE the barrier:
        // it touches no SMEM (no hazard; WAR on breg resolves at issue), so its
        // global latency overlaps the barrier wait.
        if (kb + 1 < NKB) sts_B(st_nxt);
        if (kb + 2 < NKB) ldg_B(kb + 2);
        __syncthreads();

        st_off = st_nxt;
        st_nxt += STG_B;
        if (st_nxt == NSTG * STG_B) st_nxt = 0;
    }

    // ---- epilogue ----
    #pragma unroll
    for (int mt = 0; mt < 2; mt++) {
        #pragma unroll
        for (int nt = 0; nt < 8; nt++) {
            int gm0 = m0 + wm + mt * 16 + lr;
            int gn  = n0 + wn + nt * 8 + lc * 2;
            float* c = acc[mt][nt];
            if (MODE == 0) {
                if (gm0 < cnt) {
                    __half2 h = __floats2half2_rn(silu(c[0]), silu(c[1]));
                    *reinterpret_cast<__half2*>(&g_h[(size_t)(off + gm0) * HD + gn]) = h;
                }
                if (gm0 + 8 < cnt) {
                    __half2 h = __floats2half2_rn(silu(c[2]), silu(c[3]));
                    *reinterpret_cast<__half2*>(&g_h[(size_t)(off + gm0 + 8) * HD + gn]) = h;
                }
            } else {
                if (gm0 < cnt) {
                    float2 r0 = make_float2(c[0], c[1]);
                    *reinterpret_cast<float2*>(&g_y[(size_t)(off + gm0) * DM + gn]) = r0;
                }
                if (gm0 + 8 < cnt) {
                    float2 r1 = make_float2(c[2], c[3]);
                    *reinterpret_cast<float2*>(&g_y[(size_t)(off + gm0 + 8) * DM + gn]) = r1;
                }
            }
        }
    }
}

// ---------------- kernel: deterministic combine (offsets inlined from g_cnt) ----------------
__global__ void k_combine(const float* __restrict__ x, float* __restrict__ out) {
    int t = blockIdx.x;
    int tid = threadIdx.x;

    __shared__ int sh_off[E_EXP];
    if (tid == 0) {
        int o = 0;
        #pragma unroll
        for (int i = 0; i < E_EXP; i++) { sh_off[i] = o; o += g_cnt[i]; }
    }
    __syncthreads();

    int s0 = g_tslot[2 * t + 0];
    int s1 = g_tslot[2 * t + 1];
    float w0 = g_twt[2 * t + 0];
    float w1 = g_twt[2 * t + 1];
    int r0 = sh_off[s0 >> 24] + (s0 & 0xFFFFFF);
    int r1 = sh_off[s1 >> 24] + (s1 & 0xFFFFFF);

    float4 xv = reinterpret_cast<const float4*>(x + (size_t)t * DM)[tid];
    float4 y0 = reinterpret_cast<const float4*>(g_y + (size_t)r0 * DM)[tid];
    float4 y1 = reinterpret_cast<const float4*>(g_y + (size_t)r1 * DM)[tid];
    float4 o;
    o.x = xv.x + w0 * y0.x + w1 * y1.x;
    o.y = xv.y + w0 * y0.y + w1 * y1.y;
    o.z = xv.z + w0 * y0.z + w1 * y1.z;
    o.w = xv.w + w0 * y0.w + w1 * y1.w;
    reinterpret_cast<float4*>(out + (size_t)t * DM)[tid] = o;
}

// ---------------- launcher ----------------
extern "C" void kernel_launch(void* const* d_in, const int* in_sizes, int n_in,
                              void* d_out, int out_size) {
    const float* x     = (const float*)d_in[0];
    const float* gamma = (const float*)d_in[1];
    const float* beta  = (const float*)d_in[2];
    const float* rw    = (const float*)d_in[3];
    const float* W1    = (const float*)d_in[4];
    const float* W2    = (const float*)d_in[5];
    float* out = (float*)d_out;

    cudaFuncSetAttribute(k_gemm<0>, cudaFuncAttributeMaxDynamicSharedMemorySize, DYN_BYTES);
    cudaFuncSetAttribute(k_gemm<1>, cudaFuncAttributeMaxDynamicSharedMemorySize, DYN_BYTES);

    k_init<<<1, 32>>>();
    k_ln_router<<<NTOK, 256>>>(x, gamma, beta, rw);
    // GEMM1: N=HD -> 32 n-tiles; M tiles of 128; 8 experts
    k_gemm<0><<<dim3(HD / BN, NTOK / BM, E_EXP), 256, DYN_BYTES>>>(W1);
    // GEMM2: N=DM -> 8 n-tiles
    k_gemm<1><<<dim3(DM / BN, NTOK / BM, E_EXP), 256, DYN_BYTES>>>(W2);
    k_combine<<<NTOK, 256>>>(x, out);
}

// round 16
// speedup vs baseline: 1.1192x; 1.0328x over previous
#include <cuda_runtime.h>
#include <cuda_fp16.h>
#include <cstdint>
#include <cstddef>

// ---------------- problem constants ----------------
#define E_EXP 8
#define TOPK  2
#define DM    1024
#define HD    4096
#define NTOK  4096           // B*T = 2*2048
#define LN_EPS 1e-5f
#define INV_TEMP (1.0f/1.5f)

// ---------------- GEMM tile config (R9-proven: fp16 mma.sync + ldmatrix, fused fp32 B cvt) ----
#define BM 128
#define BN 128
#define BK 32                // halves per K step
#define NSTG 4
#define ASTRH 40             // A smem row stride in halves (80B, conflict-free ldmatrix)
#define BSTRH 136            // B smem row stride in halves (272B)
#define A_STG_H (BM * ASTRH)             // 5120 halves
#define B_STG_H (BK * BSTRH)             // 4352 halves
#define STG_H   (A_STG_H + B_STG_H)      // 9472 halves = 18944 B
#define STG_B   (STG_H * 2)
#define DYN_BYTES (NSTG * STG_B)         // 75776 B (x2 CTAs/SM)

#define ROWPAD 512
#define HROWS  (NTOK * TOPK + ROWPAD)

// ---------------- device scratch (static; no allocations) ----------------
__device__ __half g_xn[(size_t)NTOK * DM];
__device__ int    g_cnt[E_EXP];
__device__ int    g_tok[E_EXP * NTOK];
__device__ int    g_tslot[NTOK * TOPK];
__device__ float  g_twt[NTOK * TOPK];
__device__ __half g_h[(size_t)HROWS * HD];            // 68 MB
__device__ float  g_y[(size_t)HROWS * DM];            // 34 MB

// ---------------- PTX helpers ----------------
__device__ __forceinline__ uint32_t smem_u32(const void* p) {
    return (uint32_t)__cvta_generic_to_shared(p);
}
__device__ __forceinline__ void cp16(uint32_t dst, const void* src, int src_bytes) {
    asm volatile("cp.async.cg.shared.global [%0], [%1], 16, %2;\n"
                 :: "r"(dst), "l"(src), "r"(src_bytes) : "memory");
}
__device__ __forceinline__ void cp_commit() {
    asm volatile("cp.async.commit_group;\n" ::: "memory");
}
__device__ __forceinline__ void sts64(uint32_t dst, uint32_t v0, uint32_t v1) {
    asm volatile("st.shared.v2.b32 [%0], {%1,%2};\n" :: "r"(dst), "r"(v0), "r"(v1) : "memory");
}
__device__ __forceinline__ void ldsm4(uint32_t* r, uint32_t addr) {
    asm volatile("ldmatrix.sync.aligned.m8n8.x4.shared.b16 {%0,%1,%2,%3}, [%4];"
                 : "=r"(r[0]), "=r"(r[1]), "=r"(r[2]), "=r"(r[3]) : "r"(addr));
}
__device__ __forceinline__ void ldsm4t(uint32_t* r, uint32_t addr) {
    asm volatile("ldmatrix.sync.aligned.m8n8.x4.trans.shared.b16 {%0,%1,%2,%3}, [%4];"
                 : "=r"(r[0]), "=r"(r[1]), "=r"(r[2]), "=r"(r[3]) : "r"(addr));
}
__device__ __forceinline__ void mma_f16(float* c, const uint32_t* a, const uint32_t* b) {
    asm volatile(
        "mma.sync.aligned.m16n8k16.row.col.f32.f16.f16.f32 "
        "{%0,%1,%2,%3}, {%4,%5,%6,%7}, {%8,%9}, {%0,%1,%2,%3};\n"
        : "+f"(c[0]), "+f"(c[1]), "+f"(c[2]), "+f"(c[3])
        : "r"(a[0]), "r"(a[1]), "r"(a[2]), "r"(a[3]), "r"(b[0]), "r"(b[1]));
}
__device__ __forceinline__ float silu(float v) { return v / (1.0f + expf(-v)); }

// inline prefix-sum of g_cnt[0..e-1] (replaces the k_off kernel)
__device__ __forceinline__ int expert_off(int e) {
    int o = 0;
    #pragma unroll
    for (int i = 0; i < E_EXP; i++) if (i < e) o += g_cnt[i];
    return o;
}

// ---------------- kernel 0: zero counters ----------------
__global__ void k_init() {
    if (threadIdx.x < E_EXP) g_cnt[threadIdx.x] = 0;
}

// ---------------- kernel 1: layernorm + router + top2 ----------------
__global__ void k_ln_router(const float* __restrict__ x,
                            const float* __restrict__ gamma,
                            const float* __restrict__ beta,
                            const float* __restrict__ rw) {
    int t = blockIdx.x;
    int tid = threadIdx.x;
    int warp = tid >> 5, lane = tid & 31;

    const float4 v = reinterpret_cast<const float4*>(x + (size_t)t * DM)[tid];
    float s  = v.x + v.y + v.z + v.w;
    float ss = v.x * v.x + v.y * v.y + v.z * v.z + v.w * v.w;
    #pragma unroll
    for (int o = 16; o; o >>= 1) {
        s  += __shfl_xor_sync(0xFFFFFFFFu, s,  o);
        ss += __shfl_xor_sync(0xFFFFFFFFu, ss, o);
    }
    __shared__ float sh_s[8], sh_ss[8];
    if (lane == 0) { sh_s[warp] = s; sh_ss[warp] = ss; }
    __syncthreads();
    float st = 0.f, sst = 0.f;
    #pragma unroll
    for (int i = 0; i < 8; i++) { st += sh_s[i]; sst += sh_ss[i]; }
    float mu   = st * (1.0f / DM);
    float var  = sst * (1.0f / DM) - mu * mu;
    float rstd = rsqrtf(var + LN_EPS);

    const float4 g = reinterpret_cast<const float4*>(gamma)[tid];
    const float4 b = reinterpret_cast<const float4*>(beta)[tid];
    float4 xn;
    xn.x = (v.x - mu) * rstd * g.x + b.x;
    xn.y = (v.y - mu) * rstd * g.y + b.y;
    xn.z = (v.z - mu) * rstd * g.z + b.z;
    xn.w = (v.w - mu) * rstd * g.w + b.w;
    {
        __half2 h0 = __floats2half2_rn(xn.x, xn.y);
        __half2 h1 = __floats2half2_rn(xn.z, xn.w);
        uint2 u;
        u.x = *reinterpret_cast<uint32_t*>(&h0);
        u.y = *reinterpret_cast<uint32_t*>(&h1);
        reinterpret_cast<uint2*>(g_xn + (size_t)t * DM)[tid] = u;
    }

    float acc[E_EXP];
    #pragma unroll
    for (int e = 0; e < E_EXP; e++) {
        const float4 w = reinterpret_cast<const float4*>(rw + (size_t)e * DM)[tid];
        acc[e] = xn.x * w.x + xn.y * w.y + xn.z * w.z + xn.w * w.w;
    }
    #pragma unroll
    for (int o = 16; o; o >>= 1) {
        #pragma unroll
        for (int e = 0; e < E_EXP; e++)
            acc[e] += __shfl_xor_sync(0xFFFFFFFFu, acc[e], o);
    }
    __shared__ float sh_l[8][E_EXP];
    if (lane == 0) {
        #pragma unroll
        for (int e = 0; e < E_EXP; e++) sh_l[warp][e] = acc[e];
    }
    __syncthreads();

    if (tid == 0) {
        float lg[E_EXP];
        #pragma unroll
        for (int e = 0; e < E_EXP; e++) {
            float a = 0.f;
            #pragma unroll
            for (int w = 0; w < 8; w++) a += sh_l[w][e];
            lg[e] = a * INV_TEMP;
        }
        float mx = lg[0];
        #pragma unroll
        for (int e = 1; e < E_EXP; e++) mx = fmaxf(mx, lg[e]);
        float p[E_EXP], sum = 0.f;
        #pragma unroll
        for (int e = 0; e < E_EXP; e++) { p[e] = expf(lg[e] - mx); sum += p[e]; }
        float inv = 1.0f / sum;
        int i1 = 0;
        #pragma unroll
        for (int e = 1; e < E_EXP; e++) if (p[e] > p[i1]) i1 = e;
        int i2 = (i1 == 0) ? 1 : 0;
        #pragma unroll
        for (int e = 0; e < E_EXP; e++) if (e != i1 && p[e] > p[i2]) i2 = e;

        int pos1 = atomicAdd(&g_cnt[i1], 1);
        int pos2 = atomicAdd(&g_cnt[i2], 1);
        g_tok[i1 * NTOK + pos1] = t;
        g_tok[i2 * NTOK + pos2] = t;
        g_tslot[2 * t + 0] = (i1 << 24) | pos1;
        g_tslot[2 * t + 1] = (i2 << 24) | pos2;
        g_twt[2 * t + 0] = p[i1] * inv;
        g_twt[2 * t + 1] = p[i2] * inv;
    }
}

// ---------------- grouped GEMM (R9-proven mainloop; fp16 mma.sync; fused fp32 B cvt) ----------
// MODE 0: g_h[off+m, :] = half( silu(xn[tok] @ W1[e]) )   (K=DM, N=HD)
// MODE 1: g_y[off+m, :] = float( g_h[off+m, :] @ W2[e] )  (K=HD, N=DM)
template <int MODE>
__global__ __launch_bounds__(256, 2)
void k_gemm(const float* __restrict__ Bw) {
    constexpr int KDIM = (MODE == 0) ? DM : HD;
    constexpr int BLD  = (MODE == 0) ? HD : DM;    // weight row stride (= N extent)
    constexpr int NKB  = KDIM / BK;

    const int e   = blockIdx.z;
    const int m0  = blockIdx.y * BM;
    const int n0  = blockIdx.x * BN;
    const int cnt = g_cnt[e];
    if (m0 >= cnt) return;
    const int off = expert_off(e);
    const int tid = threadIdx.x;

    extern __shared__ __half smh[];
    const uint32_t dyn_s = smem_u32(smh);

    __shared__ int tok_s[BM];
    if (MODE == 0) {
        if (tid < BM) {
            int m = m0 + tid;
            tok_s[tid] = (m < cnt) ? g_tok[e * NTOK + m] : -1;
        }
        __syncthreads();
    }

    // ---- A stage loader: cp.async fp16 ----
    auto load_A = [&](int kb, int s) {
        const uint32_t a_s = dyn_s + (uint32_t)s * STG_B;
        #pragma unroll
        for (int i = 0; i < 2; i++) {
            int seg = tid + i * 256;
            int row = seg >> 2;
            int j   = seg & 3;            // 16B chunk = 8 halves
            uint32_t dst = a_s + (row * ASTRH + j * 8) * 2;
            const __half* src;
            int sz = 16;
            if (MODE == 0) {
                int token = tok_s[row];
                if (token < 0) { src = g_xn; sz = 0; }
                else            src = g_xn + (size_t)token * DM + kb * BK + j * 8;
            } else {
                src = g_h + (size_t)(off + m0 + row) * HD + kb * BK + j * 8;
            }
            cp16(dst, src, sz);
        }
        cp_commit();
    };

    // ---- B: fp32 LDG into registers, cvt+STS fp16 (pipelined around MMA) ----
    const float* Bbase = Bw + (size_t)e * KDIM * BLD + n0;
    const int b_row0 = tid >> 5;          // rows b_row0, +8, +16, +24
    const int b_col4 = tid & 31;

    float4 breg[4];
    auto ldg_B = [&](int kb) {
        const float* bp = Bbase + (size_t)(kb * BK + b_row0) * BLD + b_col4 * 4;
        #pragma unroll
        for (int i = 0; i < 4; i++)
            breg[i] = *reinterpret_cast<const float4*>(bp + (size_t)(i * 8) * BLD);
    };
    const uint32_t b_sts_off = A_STG_H * 2 + (b_row0 * BSTRH + b_col4 * 4) * 2;
    auto sts_B = [&](uint32_t stage_byte) {
        const uint32_t b_s = dyn_s + stage_byte + b_sts_off;
        #pragma unroll
        for (int i = 0; i < 4; i++) {
            __half2 h0 = __floats2half2_rn(breg[i].x, breg[i].y);
            __half2 h1 = __floats2half2_rn(breg[i].z, breg[i].w);
            sts64(b_s + (i * 8 * BSTRH) * 2,
                  *reinterpret_cast<uint32_t*>(&h0), *reinterpret_cast<uint32_t*>(&h1));
        }
    };

    const int warp = tid >> 5, lane = tid & 31;
    const int wr = warp & 3, wc = warp >> 2;     // 4x2 warp grid
    const int wm = wr * 32, wn = wc * 64;        // warp tile 32x64
    const int lr = lane >> 2, lc = lane & 3;

    const uint32_t a_off0 = ((wm + (lane & 15)) * ASTRH + ((lane >> 4) * 8)) * 2;
    const uint32_t b_off0 = A_STG_H * 2 + ((lane & 15) * BSTRH + wn + ((lane >> 4) * 8)) * 2;

    float acc[2][8][4];
    #pragma unroll
    for (int mt = 0; mt < 2; mt++)
        #pragma unroll
        for (int nt = 0; nt < 8; nt++)
            #pragma unroll
            for (int i = 0; i < 4; i++) acc[mt][nt][i] = 0.f;

    // prologue
    load_A(0, 0);
    load_A(1, 1);
    load_A(2, 2);
    ldg_B(0);
    sts_B(0);
    ldg_B(1);

    uint32_t st_off = 0;
    uint32_t st_nxt = STG_B;

    for (int kb = 0; kb < NKB; kb++) {
        if (kb + 3 < NKB) {
            load_A(kb + 3, (kb + 3) & 3);
            asm volatile("cp.async.wait_group 3;\n" ::: "memory");
        } else if (kb + 2 < NKB) {
            asm volatile("cp.async.wait_group 2;\n" ::: "memory");
        } else if (kb + 1 < NKB) {
            asm volatile("cp.async.wait_group 1;\n" ::: "memory");
        } else {
            asm volatile("cp.async.wait_group 0;\n" ::: "memory");
        }
        __syncthreads();

        const uint32_t a_base = dyn_s + st_off + a_off0;
        const uint32_t b_base = dyn_s + st_off + b_off0;

        #pragma unroll
        for (int ks = 0; ks < 2; ks++) {
            const uint32_t kbyte = ks * 32;
            uint32_t af[2][4];
            #pragma unroll
            for (int mt = 0; mt < 2; mt++)
                ldsm4(af[mt], a_base + mt * (16 * ASTRH * 2) + kbyte);
            uint32_t bf[4][4];
            #pragma unroll
            for (int np = 0; np < 4; np++)
                ldsm4t(bf[np], b_base + ks * (16 * BSTRH * 2) + np * 32);
            #pragma unroll
            for (int mt = 0; mt < 2; mt++)
                #pragma unroll
                for (int nt = 0; nt < 8; nt++)
                    mma_f16(acc[mt][nt], af[mt], &bf[nt >> 1][(nt & 1) * 2]);
        }

        // R9 ordering: sts_B, trailing barrier, THEN ldg_B (after the barrier the
        // LDG hides behind other warps' MMA issue; before it, it delays arrival).
        if (kb + 1 < NKB) sts_B(st_nxt);
        __syncthreads();
        if (kb + 2 < NKB) ldg_B(kb + 2);

        st_off = st_nxt;
        st_nxt += STG_B;
        if (st_nxt == NSTG * STG_B) st_nxt = 0;
    }

    // ---- epilogue ----
    #pragma unroll
    for (int mt = 0; mt < 2; mt++) {
        #pragma unroll
        for (int nt = 0; nt < 8; nt++) {
            int gm0 = m0 + wm + mt * 16 + lr;
            int gn  = n0 + wn + nt * 8 + lc * 2;
            float* c = acc[mt][nt];
            if (MODE == 0) {
                if (gm0 < cnt) {
                    __half2 h = __floats2half2_rn(silu(c[0]), silu(c[1]));
                    *reinterpret_cast<__half2*>(&g_h[(size_t)(off + gm0) * HD + gn]) = h;
                }
                if (gm0 + 8 < cnt) {
                    __half2 h = __floats2half2_rn(silu(c[2]), silu(c[3]));
                    *reinterpret_cast<__half2*>(&g_h[(size_t)(off + gm0 + 8) * HD + gn]) = h;
                }
            } else {
                if (gm0 < cnt) {
                    float2 r0 = make_float2(c[0], c[1]);
                    *reinterpret_cast<float2*>(&g_y[(size_t)(off + gm0) * DM + gn]) = r0;
                }
                if (gm0 + 8 < cnt) {
                    float2 r1 = make_float2(c[2], c[3]);
                    *reinterpret_cast<float2*>(&g_y[(size_t)(off + gm0 + 8) * DM + gn]) = r1;
                }
            }
        }
    }
}

// ---------------- kernel: deterministic combine (offsets inlined from g_cnt) ----------------
__global__ void k_combine(const float* __restrict__ x, float* __restrict__ out) {
    int t = blockIdx.x;
    int tid = threadIdx.x;

    __shared__ int sh_off[E_EXP];
    if (tid == 0) {
        int o = 0;
        #pragma unroll
        for (int i = 0; i < E_EXP; i++) { sh_off[i] = o; o += g_cnt[i]; }
    }
    __syncthreads();

    int s0 = g_tslot[2 * t + 0];
    int s1 = g_tslot[2 * t + 1];
    float w0 = g_twt[2 * t + 0];
    float w1 = g_twt[2 * t + 1];
    int r0 = sh_off[s0 >> 24] + (s0 & 0xFFFFFF);
    int r1 = sh_off[s1 >> 24] + (s1 & 0xFFFFFF);

    float4 xv = reinterpret_cast<const float4*>(x + (size_t)t * DM)[tid];
    float4 y0 = reinterpret_cast<const float4*>(g_y + (size_t)r0 * DM)[tid];
    float4 y1 = reinterpret_cast<const float4*>(g_y + (size_t)r1 * DM)[tid];
    float4 o;
    o.x = xv.x + w0 * y0.x + w1 * y1.x;
    o.y = xv.y + w0 * y0.y + w1 * y1.y;
    o.z = xv.z + w0 * y0.z + w1 * y1.z;
    o.w = xv.w + w0 * y0.w + w1 * y1.w;
    reinterpret_cast<float4*>(out + (size_t)t * DM)[tid] = o;
}

// ---------------- launcher ----------------
extern "C" void kernel_launch(void* const* d_in, const int* in_sizes, int n_in,
                              void* d_out, int out_size) {
    const float* x     = (const float*)d_in[0];
    const float* gamma = (const float*)d_in[1];
    const float* beta  = (const float*)d_in[2];
    const float* rw    = (const float*)d_in[3];
    const float* W1    = (const float*)d_in[4];
    const float* W2    = (const float*)d_in[5];
    float* out = (float*)d_out;

    cudaFuncSetAttribute(k_gemm<0>, cudaFuncAttributeMaxDynamicSharedMemorySize, DYN_BYTES);
    cudaFuncSetAttribute(k_gemm<1>, cudaFuncAttributeMaxDynamicSharedMemorySize, DYN_BYTES);

    k_init<<<1, 32>>>();
    k_ln_router<<<NTOK, 256>>>(x, gamma, beta, rw);
    // GEMM1: N=HD -> 32 n-tiles; M tiles of 128; 8 experts
    k_gemm<0><<<dim3(HD / BN, NTOK / BM, E_EXP), 256, DYN_BYTES>>>(W1);
    // GEMM2: N=DM -> 8 n-tiles
    k_gemm<1><<<dim3(DM / BN, NTOK / BM, E_EXP), 256, DYN_BYTES>>>(W2);
    k_combine<<<NTOK, 256>>>(x, out);
}